// round 9
// baseline (speedup 1.0000x reference)
#include <cuda_runtime.h>
#include <cuda_bf16.h>
#include <cstdint>

#define NODES 50000
#define EDGES 800000
#define HID   128
#define CAP   128
#define OVFMAX 65536
#define NTILES 391            // ceil(50000/128)

// ---------------------------------------------------------------------------
// Device-global scratch (no allocations allowed)
// ---------------------------------------------------------------------------
__device__ float g_h2[(size_t)NODES * HID];
__device__ float g_P[(size_t)NODES * HID];
__device__ float g_Q[(size_t)NODES * HID];
__device__ int   g_cnt[NODES];
__device__ int   g_bucket[(size_t)NODES * CAP];
__device__ int2  g_ovf[OVFMAX];
__device__ int   g_novf;

// bf16 hi/lo "image" arrays: per 128-row tile, 32 KB contiguous, element (r,k)
// at byte off = r*256 + ((k>>6)<<7) + (((k&63)<<1) ^ ((r&7)<<4)).
__device__ uint4 g_xHi[(size_t)NTILES * 2048];
__device__ uint4 g_xLo[(size_t)NTILES * 2048];
__device__ uint4 g_hHi[(size_t)NTILES * 2048];
__device__ uint4 g_hLo[(size_t)NTILES * 2048];
__device__ uint4 g_sHi[(size_t)NTILES * 2048];
__device__ uint4 g_sLo[(size_t)NTILES * 2048];

// Weight images (transposed, hi block 32KB then lo block 32KB)
__device__ uint4 g_iWin[4096];
__device__ uint4 g_iW1a[4096];
__device__ uint4 g_iW1b[4096];
__device__ uint4 g_iW2 [4096];

// ---------------------------------------------------------------------------
__device__ __forceinline__ uint32_t smem_u32(const void* p) {
    uint32_t a;
    asm("{ .reg .u64 t; cvta.to.shared.u64 t, %1; cvt.u32.u64 %0, t; }"
        : "=r"(a) : "l"(p));
    return a;
}
__device__ __forceinline__ unsigned packbf(float x, float y) {
    __nv_bfloat162 t = __floats2bfloat162_rn(x, y);
    return *reinterpret_cast<unsigned*>(&t);
}
__device__ __forceinline__ void ldsm4(unsigned* r, uint32_t addr) {
    asm volatile("ldmatrix.sync.aligned.m8n8.x4.shared.b16 {%0,%1,%2,%3}, [%4];"
                 : "=r"(r[0]), "=r"(r[1]), "=r"(r[2]), "=r"(r[3]) : "r"(addr));
}
__device__ __forceinline__ void mma16816(float* d, const unsigned* a,
                                         unsigned b0, unsigned b1) {
    asm volatile(
        "mma.sync.aligned.m16n8k16.row.col.f32.bf16.bf16.f32 "
        "{%0,%1,%2,%3},{%4,%5,%6,%7},{%8,%9},{%0,%1,%2,%3};"
        : "+f"(d[0]), "+f"(d[1]), "+f"(d[2]), "+f"(d[3])
        : "r"(a[0]), "r"(a[1]), "r"(a[2]), "r"(a[3]), "r"(b0), "r"(b1));
}
__device__ __forceinline__ void cpa16(uint32_t dst, const void* src) {
    asm volatile("cp.async.cg.shared.global [%0], [%1], 16;"
                 :: "r"(dst), "l"(src));
}
#define CP_COMMIT() asm volatile("cp.async.commit_group;" ::: "memory")
#define CP_WAIT0()  asm volatile("cp.async.wait_group 0;" ::: "memory")

__device__ __forceinline__ uint32_t img_off(int r, int k) {
    return (uint32_t)r * 256 + ((k >> 6) << 7) + ((((k & 63) << 1)) ^ ((r & 7) << 4));
}

// ---------------------------------------------------------------------------
// Prep: weight images
// ---------------------------------------------------------------------------
__device__ __forceinline__ void img_write(uint4* img, int n, int k, float v) {
    __nv_bfloat16 hi = __float2bfloat16(v);
    float hf = __bfloat162float(hi);
    __nv_bfloat16 lo = __float2bfloat16(v - hf);
    uint32_t off = img_off(n, k);
    __nv_bfloat16* p = (__nv_bfloat16*)img;
    p[off >> 1]               = hi;
    p[128 * 128 + (off >> 1)] = lo;
}

__global__ void __launch_bounds__(256)
prep_kernel(const float* __restrict__ W_in, const float* __restrict__ W1,
            const float* __restrict__ W2)
{
    int idx = blockIdx.x * blockDim.x + threadIdx.x;
    int n = (idx >> 7) & 127, k = idx & 127;
    if (idx < 16384) {
        img_write(g_iWin, n, k, W_in[k * 128 + n]);
    } else if (idx < 32768) {
        img_write(g_iW1a, n, k, W1[k * 128 + n]);
    } else if (idx < 49152) {
        img_write(g_iW1b, n, k, W1[(128 + k) * 128 + n]);
    } else if (idx < 65536) {
        img_write(g_iW2, n, k, W2[k * 128 + n]);
    }
}

// ---------------------------------------------------------------------------
// convert_x: x fp32 -> hi/lo bf16 images (zero-pad rows >= M)
// One thread handles a quarter row (8 float4).
// ---------------------------------------------------------------------------
__global__ void __launch_bounds__(256)
convert_x(const float* __restrict__ x, uint4* __restrict__ hi,
          uint4* __restrict__ lo, int M)
{
    int idx = blockIdx.x * blockDim.x + threadIdx.x;   // [0, NTILES*512)
    int sr = idx >> 2;
    if (sr >= NTILES * 128) return;
    int sq = idx & 3;
    int tile = sr >> 7, r = sr & 127;
    const float4* Ar = (const float4*)x + (size_t)sr * 32 + sq * 8;
    char* hB = (char*)hi + (size_t)tile * 32768;
    char* lB = (char*)lo + (size_t)tile * 32768;
#pragma unroll
    for (int j = 0; j < 8; ++j) {
        float4 v = make_float4(0.f, 0.f, 0.f, 0.f);
        if (sr < M) v = Ar[j];
        float hx = __bfloat162float(__float2bfloat16(v.x));
        float hy = __bfloat162float(__float2bfloat16(v.y));
        float hz = __bfloat162float(__float2bfloat16(v.z));
        float hw = __bfloat162float(__float2bfloat16(v.w));
        uint32_t off = img_off(r, (sq * 8 + j) * 4);
        *(uint2*)(hB + off) = make_uint2(packbf(v.x, v.y), packbf(v.z, v.w));
        *(uint2*)(lB + off) = make_uint2(packbf(v.x - hx, v.y - hy),
                                         packbf(v.z - hz, v.w - hw));
    }
}

// ---------------------------------------------------------------------------
// Shared mainloop: 3-term bf16 split over one 128x128 tile.
// ---------------------------------------------------------------------------
__device__ __forceinline__ void tile_mainloop(
    float acc[2][4][4], uint32_t sAh, uint32_t sAl, uint32_t sWh, uint32_t sWl,
    int warpM, int warpN, int fi, int fswz, int fk8)
{
#pragma unroll
    for (int mt = 0; mt < 2; ++mt)
#pragma unroll
        for (int ns = 0; ns < 4; ++ns)
#pragma unroll
            for (int e = 0; e < 4; ++e) acc[mt][ns][e] = 0.f;

#pragma unroll
    for (int t = 0; t < 3; ++t) {
        const uint32_t ab = (t == 1) ? sAl : sAh;
        const uint32_t wb = (t == 2) ? sWl : sWh;
#pragma unroll
        for (int ks = 0; ks < 8; ++ks) {
            const int k8 = ks * 16 + fk8;
            const uint32_t koff = ((k8 >> 6) << 7) + (((k8 & 63) << 1) ^ fswz);
            unsigned bt[2][4], a[2][4];
#pragma unroll
            for (int nt = 0; nt < 2; ++nt)
                ldsm4(bt[nt], wb + (uint32_t)(warpN * 32 + nt * 16 + fi) * 256 + koff);
#pragma unroll
            for (int mt = 0; mt < 2; ++mt)
                ldsm4(a[mt], ab + (uint32_t)(warpM * 32 + mt * 16 + fi) * 256 + koff);
#pragma unroll
            for (int mt = 0; mt < 2; ++mt)
#pragma unroll
                for (int nt = 0; nt < 2; ++nt) {
                    mma16816(acc[mt][nt * 2],     a[mt], bt[nt][0], bt[nt][2]);
                    mma16816(acc[mt][nt * 2 + 1], a[mt], bt[nt][1], bt[nt][3]);
                }
        }
    }
}

// fp32 epilogue (optional rowcnt-scaled bias + relu)
__device__ __forceinline__ void epi_f32(
    float acc[2][4][4], float* __restrict__ C, const float* __restrict__ bias,
    const int* __restrict__ rowcnt, int m0, int M, int do_relu,
    int warpM, int warpN, int L)
{
#pragma unroll
    for (int mt = 0; mt < 2; ++mt) {
        int gr0 = m0 + warpM * 32 + mt * 16 + (L >> 2);
        int gr1 = gr0 + 8;
        float sc0 = 1.f, sc1 = 1.f;
        if (rowcnt) {
            if (gr0 < M) sc0 = (float)rowcnt[gr0];
            if (gr1 < M) sc1 = (float)rowcnt[gr1];
        }
#pragma unroll
        for (int ns = 0; ns < 4; ++ns) {
            int c = warpN * 32 + ns * 8 + (L & 3) * 2;
            float b0 = bias ? bias[c]     : 0.f;
            float b1 = bias ? bias[c + 1] : 0.f;
            float v00 = acc[mt][ns][0] + sc0 * b0;
            float v01 = acc[mt][ns][1] + sc0 * b1;
            float v10 = acc[mt][ns][2] + sc1 * b0;
            float v11 = acc[mt][ns][3] + sc1 * b1;
            if (do_relu) {
                v00 = fmaxf(v00, 0.f); v01 = fmaxf(v01, 0.f);
                v10 = fmaxf(v10, 0.f); v11 = fmaxf(v11, 0.f);
            }
            if (gr0 < M) *(float2*)(C + (size_t)gr0 * 128 + c) = make_float2(v00, v01);
            if (gr1 < M) *(float2*)(C + (size_t)gr1 * 128 + c) = make_float2(v10, v11);
        }
    }
}

// ---------------------------------------------------------------------------
// gemm_img: image input, cp.async double-buffered.
// smem: [A0 64K][A1 64K][W 64K] = 192 KB.
// Output: if outHi != null -> relu+bias, split to hi/lo images.
//         else             -> fp32 C with optional rowcnt*bias + relu.
// ---------------------------------------------------------------------------
__global__ void __launch_bounds__(512, 1)
gemm_img(const uint4* __restrict__ hiImg, const uint4* __restrict__ loImg,
         const uint4* __restrict__ Wimg, const float* __restrict__ bias,
         const int* __restrict__ rowcnt, float* __restrict__ C,
         uint4* __restrict__ outHi, uint4* __restrict__ outLo,
         int M, int ntiles, int do_relu)
{
    extern __shared__ char smem[];
    const uint32_t sb = smem_u32(smem);
    const uint32_t sW = sb + 131072;

    const int tid = threadIdx.x;
    const int wid = tid >> 5;
    const int L   = tid & 31;
    const int warpM = wid >> 2, warpN = wid & 3;
    const int fi = L & 15, fswz = (fi & 7) << 4, fk8 = (L >> 4) * 8;

    for (int i = tid; i < 4096; i += 512) cpa16(sW + i * 16, Wimg + i);
    {
        int t0 = blockIdx.x;
        if (t0 < ntiles) {
            const uint4* sH = hiImg + (size_t)t0 * 2048;
            const uint4* sL = loImg + (size_t)t0 * 2048;
            for (int i = tid; i < 2048; i += 512) {
                cpa16(sb + i * 16, sH + i);
                cpa16(sb + 32768 + i * 16, sL + i);
            }
        }
    }
    CP_COMMIT();

    int cur = 0;
    for (int tile = blockIdx.x; tile < ntiles; tile += gridDim.x) {
        CP_WAIT0();
        __syncthreads();

        int nxt = tile + gridDim.x;
        if (nxt < ntiles) {
            uint32_t dst = sb + (cur ^ 1) * 65536;
            const uint4* sH = hiImg + (size_t)nxt * 2048;
            const uint4* sL = loImg + (size_t)nxt * 2048;
            for (int i = tid; i < 2048; i += 512) {
                cpa16(dst + i * 16, sH + i);
                cpa16(dst + 32768 + i * 16, sL + i);
            }
        }
        CP_COMMIT();

        const uint32_t sAh = sb + cur * 65536;
        float acc[2][4][4];
        tile_mainloop(acc, sAh, sAh + 32768, sW, sW + 32768,
                      warpM, warpN, fi, fswz, fk8);

        const int m0 = tile * 128;
        if (outHi) {
            char* hB = (char*)outHi + (size_t)tile * 32768;
            char* lB = (char*)outLo + (size_t)tile * 32768;
#pragma unroll
            for (int mt = 0; mt < 2; ++mt) {
                int r0 = warpM * 32 + mt * 16 + (L >> 2);
                int r1 = r0 + 8;
#pragma unroll
                for (int ns = 0; ns < 4; ++ns) {
                    int c = warpN * 32 + ns * 8 + (L & 3) * 2;
                    float b0 = bias[c], b1 = bias[c + 1];
                    float v00 = fmaxf(acc[mt][ns][0] + b0, 0.f);
                    float v01 = fmaxf(acc[mt][ns][1] + b1, 0.f);
                    float v10 = fmaxf(acc[mt][ns][2] + b0, 0.f);
                    float v11 = fmaxf(acc[mt][ns][3] + b1, 0.f);
                    if (m0 + r0 < M) {
                        uint32_t off = img_off(r0, c);
                        float h0 = __bfloat162float(__float2bfloat16(v00));
                        float h1 = __bfloat162float(__float2bfloat16(v01));
                        *(unsigned*)(hB + off) = packbf(v00, v01);
                        *(unsigned*)(lB + off) = packbf(v00 - h0, v01 - h1);
                    }
                    if (m0 + r1 < M) {
                        uint32_t off = img_off(r1, c);
                        float h0 = __bfloat162float(__float2bfloat16(v10));
                        float h1 = __bfloat162float(__float2bfloat16(v11));
                        *(unsigned*)(hB + off) = packbf(v10, v11);
                        *(unsigned*)(lB + off) = packbf(v10 - h0, v11 - h1);
                    }
                }
            }
        } else {
            epi_f32(acc, C, bias, rowcnt, m0, M, do_relu, warpM, warpN, L);
        }
        cur ^= 1;
    }
}

// ---------------------------------------------------------------------------
// gemm_pq: fused P and Q GEMM. A (h image) staged once per tile;
// both W1a and W1b resident. smem: [A 64K][Wa 64K][Wb 64K] = 192 KB.
// ---------------------------------------------------------------------------
__global__ void __launch_bounds__(512, 1)
gemm_pq(const uint4* __restrict__ hiImg, const uint4* __restrict__ loImg,
        const uint4* __restrict__ Wa, const uint4* __restrict__ Wb,
        const float* __restrict__ b1, float* __restrict__ P,
        float* __restrict__ Q, int M, int ntiles)
{
    extern __shared__ char smem[];
    const uint32_t sb  = smem_u32(smem);
    const uint32_t sWa = sb + 65536;
    const uint32_t sWb = sb + 131072;

    const int tid = threadIdx.x;
    const int wid = tid >> 5;
    const int L   = tid & 31;
    const int warpM = wid >> 2, warpN = wid & 3;
    const int fi = L & 15, fswz = (fi & 7) << 4, fk8 = (L >> 4) * 8;

    for (int i = tid; i < 4096; i += 512) {
        cpa16(sWa + i * 16, Wa + i);
        cpa16(sWb + i * 16, Wb + i);
    }
    CP_COMMIT();

    for (int tile = blockIdx.x; tile < ntiles; tile += gridDim.x) {
        __syncthreads();   // prior-iter A readers done
        {
            const uint4* sH = hiImg + (size_t)tile * 2048;
            const uint4* sL = loImg + (size_t)tile * 2048;
            for (int i = tid; i < 2048; i += 512) {
                cpa16(sb + i * 16, sH + i);
                cpa16(sb + 32768 + i * 16, sL + i);
            }
        }
        CP_COMMIT();
        CP_WAIT0();
        __syncthreads();

        const int m0 = tile * 128;
        float acc[2][4][4];
        tile_mainloop(acc, sb, sb + 32768, sWa, sWa + 32768,
                      warpM, warpN, fi, fswz, fk8);
        epi_f32(acc, P, b1, nullptr, m0, M, 0, warpM, warpN, L);

        tile_mainloop(acc, sb, sb + 32768, sWb, sWb + 32768,
                      warpM, warpN, fi, fswz, fk8);
        epi_f32(acc, Q, nullptr, nullptr, m0, M, 0, warpM, warpN, L);
    }
}

// ---------------------------------------------------------------------------
__global__ void __launch_bounds__(256)
zero_kernel()
{
    int idx = blockIdx.x * blockDim.x + threadIdx.x;
    int stride = gridDim.x * blockDim.x;
    for (int i = idx; i < NODES; i += stride) g_cnt[i] = 0;
    if (idx == 0) g_novf = 0;
}

__global__ void __launch_bounds__(256)
bucket_kernel(const int* __restrict__ ei)
{
    int e = blockIdx.x * blockDim.x + threadIdx.x;
    if (e >= EDGES) return;
    int s = ei[e];
    int d = ei[EDGES + e];
    int slot = atomicAdd(&g_cnt[d], 1);
    if (slot < CAP) {
        g_bucket[(size_t)d * CAP + slot] = s;
    } else {
        int o = atomicAdd(&g_novf, 1);
        if (o < OVFMAX) g_ovf[o] = make_int2(s, d);
    }
}

// Warp per node: S[d] = sum relu(P[d]+Q[src]); write S as bf16 hi/lo images.
__global__ void __launch_bounds__(256)
node_kernel()
{
    int d    = (blockIdx.x * blockDim.x + threadIdx.x) >> 5;
    int lane = threadIdx.x & 31;
    if (d >= NODES) return;

    int n = g_cnt[d];
    if (n > CAP) n = CAP;

    float4 p = ((const float4*)(g_P + (size_t)d * HID))[lane];
    float4 acc = make_float4(0.f, 0.f, 0.f, 0.f);
    const int* bkt = g_bucket + (size_t)d * CAP;
#pragma unroll 2
    for (int i = 0; i < n; ++i) {
        int s = __ldg(bkt + i);
        float4 q = ((const float4*)(g_Q + (size_t)s * HID))[lane];
        acc.x += fmaxf(p.x + q.x, 0.f);
        acc.y += fmaxf(p.y + q.y, 0.f);
        acc.z += fmaxf(p.z + q.z, 0.f);
        acc.w += fmaxf(p.w + q.w, 0.f);
    }
    int r = d & 127;
    uint32_t off = img_off(r, lane * 4);
    char* hB = (char*)g_sHi + (size_t)(d >> 7) * 32768;
    char* lB = (char*)g_sLo + (size_t)(d >> 7) * 32768;
    float hx = __bfloat162float(__float2bfloat16(acc.x));
    float hy = __bfloat162float(__float2bfloat16(acc.y));
    float hz = __bfloat162float(__float2bfloat16(acc.z));
    float hw = __bfloat162float(__float2bfloat16(acc.w));
    *(uint2*)(hB + off) = make_uint2(packbf(acc.x, acc.y), packbf(acc.z, acc.w));
    *(uint2*)(lB + off) = make_uint2(packbf(acc.x - hx, acc.y - hy),
                                     packbf(acc.z - hz, acc.w - hw));
}

// Serial overflow fixup (single warp; expected empty). RMW on S images.
__global__ void __launch_bounds__(32)
fixup_kernel()
{
    int total = g_novf;
    if (total > OVFMAX) total = OVFMAX;
    int lane = threadIdx.x;
    for (int j = 0; j < total; ++j) {
        int2 e = g_ovf[j];
        float4 p = ((const float4*)(g_P + (size_t)e.y * HID))[lane];
        float4 q = ((const float4*)(g_Q + (size_t)e.x * HID))[lane];
        int r = e.y & 127;
        uint32_t off = img_off(r, lane * 4);
        char* hB = (char*)g_sHi + (size_t)(e.y >> 7) * 32768;
        char* lB = (char*)g_sLo + (size_t)(e.y >> 7) * 32768;
        uint2 hh = *(uint2*)(hB + off);
        uint2 ll = *(uint2*)(lB + off);
        __nv_bfloat162 h0 = *(__nv_bfloat162*)&hh.x, h1 = *(__nv_bfloat162*)&hh.y;
        __nv_bfloat162 l0 = *(__nv_bfloat162*)&ll.x, l1 = *(__nv_bfloat162*)&ll.y;
        float vx = __bfloat162float(h0.x) + __bfloat162float(l0.x) + fmaxf(p.x + q.x, 0.f);
        float vy = __bfloat162float(h0.y) + __bfloat162float(l0.y) + fmaxf(p.y + q.y, 0.f);
        float vz = __bfloat162float(h1.x) + __bfloat162float(l1.x) + fmaxf(p.z + q.z, 0.f);
        float vw = __bfloat162float(h1.y) + __bfloat162float(l1.y) + fmaxf(p.w + q.w, 0.f);
        float hx = __bfloat162float(__float2bfloat16(vx));
        float hy = __bfloat162float(__float2bfloat16(vy));
        float hz = __bfloat162float(__float2bfloat16(vz));
        float hw = __bfloat162float(__float2bfloat16(vw));
        *(uint2*)(hB + off) = make_uint2(packbf(vx, vy), packbf(vz, vw));
        *(uint2*)(lB + off) = make_uint2(packbf(vx - hx, vy - hy),
                                         packbf(vz - hz, vw - hw));
        __syncwarp();
    }
}

__global__ void __launch_bounds__(256)
out_kernel(const float* __restrict__ H2, const float* __restrict__ Wc,
           const float* __restrict__ bc, float* __restrict__ out)
{
    int gw   = (blockIdx.x * blockDim.x + threadIdx.x) >> 5;
    int lane = threadIdx.x & 31;
    if (gw >= NODES) return;

    float4 hv  = ((const float4*)(H2 + (size_t)gw * HID))[lane];
    float4 w01 = ((const float4*)Wc)[lane * 2];
    float4 w23 = ((const float4*)Wc)[lane * 2 + 1];

    float a0 = hv.x * w01.x + hv.y * w01.z + hv.z * w23.x + hv.w * w23.z;
    float a1 = hv.x * w01.y + hv.y * w01.w + hv.z * w23.y + hv.w * w23.w;
#pragma unroll
    for (int off = 16; off > 0; off >>= 1) {
        a0 += __shfl_xor_sync(0xffffffffu, a0, off);
        a1 += __shfl_xor_sync(0xffffffffu, a1, off);
    }
    if (lane == 0) {
        out[(size_t)gw * 2]     = a0 + bc[0];
        out[(size_t)gw * 2 + 1] = a1 + bc[1];
    }
}

// ---------------------------------------------------------------------------
extern "C" void kernel_launch(void* const* d_in, const int* in_sizes, int n_in,
                              void* d_out, int out_size)
{
    const float* x    = (const float*)d_in[0];
    const int*   ei   = (const int*)d_in[1];
    const float* W_in = (const float*)d_in[2];
    const float* b_in = (const float*)d_in[3];
    const float* W1   = (const float*)d_in[4];
    const float* b1   = (const float*)d_in[5];
    const float* W2   = (const float*)d_in[6];
    const float* b2   = (const float*)d_in[7];
    const float* Wc   = (const float*)d_in[8];
    const float* bc   = (const float*)d_in[9];
    float*       out  = (float*)d_out;

    void *ph2, *pP, *pQ, *pcnt, *pWin, *pW1a, *pW1b, *pW2;
    void *pxHi, *pxLo, *phHi, *phLo, *psHi, *psLo;
    cudaGetSymbolAddress(&ph2,  g_h2);
    cudaGetSymbolAddress(&pP,   g_P);
    cudaGetSymbolAddress(&pQ,   g_Q);
    cudaGetSymbolAddress(&pcnt, g_cnt);
    cudaGetSymbolAddress(&pWin, g_iWin);
    cudaGetSymbolAddress(&pW1a, g_iW1a);
    cudaGetSymbolAddress(&pW1b, g_iW1b);
    cudaGetSymbolAddress(&pW2,  g_iW2);
    cudaGetSymbolAddress(&pxHi, g_xHi);
    cudaGetSymbolAddress(&pxLo, g_xLo);
    cudaGetSymbolAddress(&phHi, g_hHi);
    cudaGetSymbolAddress(&phLo, g_hLo);
    cudaGetSymbolAddress(&psHi, g_sHi);
    cudaGetSymbolAddress(&psLo, g_sLo);

    cudaFuncSetAttribute(gemm_img, cudaFuncAttributeMaxDynamicSharedMemorySize,
                         192 * 1024);
    cudaFuncSetAttribute(gemm_pq, cudaFuncAttributeMaxDynamicSharedMemorySize,
                         192 * 1024);

    const int M = NODES;
    const int GRID = 148;

    prep_kernel<<<256, 256>>>(W_in, W1, W2);
    zero_kernel<<<256, 256>>>();
    bucket_kernel<<<(EDGES + 255) / 256, 256>>>(ei);
    convert_x<<<(NTILES * 512 + 255) / 256, 256>>>(x, (uint4*)pxHi,
                                                   (uint4*)pxLo, M);

    // 1) h images = split(relu(ximg @ Win + b_in))
    gemm_img<<<GRID, 512, 192 * 1024>>>((const uint4*)pxHi, (const uint4*)pxLo,
                                        (const uint4*)pWin, b_in, nullptr,
                                        nullptr, (uint4*)phHi, (uint4*)phLo,
                                        M, NTILES, 1);
    // 2+3) P = h @ W1a + b1 ; Q = h @ W1b   (fused)
    gemm_pq<<<GRID, 512, 192 * 1024>>>((const uint4*)phHi, (const uint4*)phLo,
                                       (const uint4*)pW1a, (const uint4*)pW1b,
                                       b1, (float*)pP, (float*)pQ, M, NTILES);
    // 4) S images = split( sum_e relu(P[d]+Q[s]) )
    node_kernel<<<(NODES * 32 + 255) / 256, 256>>>();
    fixup_kernel<<<1, 32>>>();
    // 5) h2 = relu(S @ W2 + deg*b2)
    gemm_img<<<GRID, 512, 192 * 1024>>>((const uint4*)psHi, (const uint4*)psLo,
                                        (const uint4*)pW2, b2, (const int*)pcnt,
                                        (float*)ph2, nullptr, nullptr,
                                        M, NTILES, 1);
    // 6) out = h2 @ Wc + bc
    out_kernel<<<(NODES * 32 + 255) / 256, 256>>>((const float*)ph2, Wc, bc, out);
}

// round 10
// speedup vs baseline: 1.1021x; 1.1021x over previous
#include <cuda_runtime.h>
#include <cuda_bf16.h>
#include <cstdint>

#define NODES 50000
#define EDGES 800000
#define HID   128
#define CAP   128
#define OVFMAX 65536
#define NTILES 391            // ceil(50000/128)

// ---------------------------------------------------------------------------
// Device-global scratch (no allocations allowed)
// ---------------------------------------------------------------------------
__device__ float g_h2[(size_t)NODES * HID];
__device__ float g_P[(size_t)NODES * HID];
__device__ float g_Q[(size_t)NODES * HID];
__device__ int   g_cnt[NODES];
__device__ int   g_bucket[(size_t)NODES * CAP];
__device__ int2  g_ovf[OVFMAX];
__device__ int   g_novf;

// bf16 hi/lo "image" arrays: per 128-row tile, 32 KB contiguous, element (r,k)
// at byte off = r*256 + ((k>>6)<<7) + (((k&63)<<1) ^ ((r&7)<<4)).
__device__ uint4 g_hHi[(size_t)NTILES * 2048];
__device__ uint4 g_hLo[(size_t)NTILES * 2048];
__device__ uint4 g_sHi[(size_t)NTILES * 2048];
__device__ uint4 g_sLo[(size_t)NTILES * 2048];

// Weight images (transposed, hi block 32KB then lo block 32KB)
__device__ uint4 g_iWin[4096];
__device__ uint4 g_iW1a[4096];
__device__ uint4 g_iW1b[4096];
__device__ uint4 g_iW2 [4096];

// ---------------------------------------------------------------------------
__device__ __forceinline__ uint32_t smem_u32(const void* p) {
    uint32_t a;
    asm("{ .reg .u64 t; cvta.to.shared.u64 t, %1; cvt.u32.u64 %0, t; }"
        : "=r"(a) : "l"(p));
    return a;
}
__device__ __forceinline__ unsigned packbf(float x, float y) {
    __nv_bfloat162 t = __floats2bfloat162_rn(x, y);
    return *reinterpret_cast<unsigned*>(&t);
}
__device__ __forceinline__ void ldsm4(unsigned* r, uint32_t addr) {
    asm volatile("ldmatrix.sync.aligned.m8n8.x4.shared.b16 {%0,%1,%2,%3}, [%4];"
                 : "=r"(r[0]), "=r"(r[1]), "=r"(r[2]), "=r"(r[3]) : "r"(addr));
}
__device__ __forceinline__ void mma16816(float* d, const unsigned* a,
                                         unsigned b0, unsigned b1) {
    asm volatile(
        "mma.sync.aligned.m16n8k16.row.col.f32.bf16.bf16.f32 "
        "{%0,%1,%2,%3},{%4,%5,%6,%7},{%8,%9},{%0,%1,%2,%3};"
        : "+f"(d[0]), "+f"(d[1]), "+f"(d[2]), "+f"(d[3])
        : "r"(a[0]), "r"(a[1]), "r"(a[2]), "r"(a[3]), "r"(b0), "r"(b1));
}
__device__ __forceinline__ void cpa16(uint32_t dst, const void* src) {
    asm volatile("cp.async.cg.shared.global [%0], [%1], 16;"
                 :: "r"(dst), "l"(src));
}
// cp.async with runtime src-size (0 -> zero-fill)
__device__ __forceinline__ void cpa16z(uint32_t dst, const void* src, int sz) {
    asm volatile("cp.async.cg.shared.global [%0], [%1], 16, %2;"
                 :: "r"(dst), "l"(src), "r"(sz));
}
#define CP_COMMIT() asm volatile("cp.async.commit_group;" ::: "memory")
#define CP_WAIT0()  asm volatile("cp.async.wait_group 0;" ::: "memory")

__device__ __forceinline__ uint32_t img_off(int r, int k) {
    return (uint32_t)r * 256 + ((k >> 6) << 7) + ((((k & 63) << 1)) ^ ((r & 7) << 4));
}
// fp32 staging swizzle: row r (512B), 16B chunk cc in [0,32)
__device__ __forceinline__ uint32_t f32_off(int r, int cc) {
    return (uint32_t)r * 512 +
           (((uint32_t)cc * 16) ^ ((r & 7) << 4) ^ ((cc >> 3) << 4));
}

// ---------------------------------------------------------------------------
// Prep: weight images
// ---------------------------------------------------------------------------
__device__ __forceinline__ void img_write(uint4* img, int n, int k, float v) {
    __nv_bfloat16 hi = __float2bfloat16(v);
    float hf = __bfloat162float(hi);
    __nv_bfloat16 lo = __float2bfloat16(v - hf);
    uint32_t off = img_off(n, k);
    __nv_bfloat16* p = (__nv_bfloat16*)img;
    p[off >> 1]               = hi;
    p[128 * 128 + (off >> 1)] = lo;
}

__global__ void __launch_bounds__(256)
prep_kernel(const float* __restrict__ W_in, const float* __restrict__ W1,
            const float* __restrict__ W2)
{
    int idx = blockIdx.x * blockDim.x + threadIdx.x;
    int n = (idx >> 7) & 127, k = idx & 127;
    if (idx < 16384) {
        img_write(g_iWin, n, k, W_in[k * 128 + n]);
    } else if (idx < 32768) {
        img_write(g_iW1a, n, k, W1[k * 128 + n]);
    } else if (idx < 49152) {
        img_write(g_iW1b, n, k, W1[(128 + k) * 128 + n]);
    } else if (idx < 65536) {
        img_write(g_iW2, n, k, W2[k * 128 + n]);
    }
}

// ---------------------------------------------------------------------------
// Shared mainloop: 3-term bf16 split over one 128x128 tile.
// ---------------------------------------------------------------------------
__device__ __forceinline__ void tile_mainloop(
    float acc[2][4][4], uint32_t sAh, uint32_t sAl, uint32_t sWh, uint32_t sWl,
    int warpM, int warpN, int fi, int fswz, int fk8)
{
#pragma unroll
    for (int mt = 0; mt < 2; ++mt)
#pragma unroll
        for (int ns = 0; ns < 4; ++ns)
#pragma unroll
            for (int e = 0; e < 4; ++e) acc[mt][ns][e] = 0.f;

#pragma unroll
    for (int t = 0; t < 3; ++t) {
        const uint32_t ab = (t == 1) ? sAl : sAh;
        const uint32_t wb = (t == 2) ? sWl : sWh;
#pragma unroll
        for (int ks = 0; ks < 8; ++ks) {
            const int k8 = ks * 16 + fk8;
            const uint32_t koff = ((k8 >> 6) << 7) + (((k8 & 63) << 1) ^ fswz);
            unsigned bt[2][4], a[2][4];
#pragma unroll
            for (int nt = 0; nt < 2; ++nt)
                ldsm4(bt[nt], wb + (uint32_t)(warpN * 32 + nt * 16 + fi) * 256 + koff);
#pragma unroll
            for (int mt = 0; mt < 2; ++mt)
                ldsm4(a[mt], ab + (uint32_t)(warpM * 32 + mt * 16 + fi) * 256 + koff);
#pragma unroll
            for (int mt = 0; mt < 2; ++mt)
#pragma unroll
                for (int nt = 0; nt < 2; ++nt) {
                    mma16816(acc[mt][nt * 2],     a[mt], bt[nt][0], bt[nt][2]);
                    mma16816(acc[mt][nt * 2 + 1], a[mt], bt[nt][1], bt[nt][3]);
                }
        }
    }
}

// fp32 epilogue (optional rowcnt-scaled bias + relu)
__device__ __forceinline__ void epi_f32(
    float acc[2][4][4], float* __restrict__ C, const float* __restrict__ bias,
    const int* __restrict__ rowcnt, int m0, int M, int do_relu,
    int warpM, int warpN, int L)
{
#pragma unroll
    for (int mt = 0; mt < 2; ++mt) {
        int gr0 = m0 + warpM * 32 + mt * 16 + (L >> 2);
        int gr1 = gr0 + 8;
        float sc0 = 1.f, sc1 = 1.f;
        if (rowcnt) {
            if (gr0 < M) sc0 = (float)rowcnt[gr0];
            if (gr1 < M) sc1 = (float)rowcnt[gr1];
        }
#pragma unroll
        for (int ns = 0; ns < 4; ++ns) {
            int c = warpN * 32 + ns * 8 + (L & 3) * 2;
            float b0 = bias ? bias[c]     : 0.f;
            float b1 = bias ? bias[c + 1] : 0.f;
            float v00 = acc[mt][ns][0] + sc0 * b0;
            float v01 = acc[mt][ns][1] + sc0 * b1;
            float v10 = acc[mt][ns][2] + sc1 * b0;
            float v11 = acc[mt][ns][3] + sc1 * b1;
            if (do_relu) {
                v00 = fmaxf(v00, 0.f); v01 = fmaxf(v01, 0.f);
                v10 = fmaxf(v10, 0.f); v11 = fmaxf(v11, 0.f);
            }
            if (gr0 < M) *(float2*)(C + (size_t)gr0 * 128 + c) = make_float2(v00, v01);
            if (gr1 < M) *(float2*)(C + (size_t)gr1 * 128 + c) = make_float2(v10, v11);
        }
    }
}

// ---------------------------------------------------------------------------
// gemm_xa: fp32 A input via double-buffered cp.async; in-smem convert to
// hi/lo images (in place); mainloop; epilogue -> relu+bias, hi/lo images.
// smem: [A0 64K][A1 64K][W 64K] = 192 KB.
// ---------------------------------------------------------------------------
__global__ void __launch_bounds__(512, 1)
gemm_xa(const float* __restrict__ A, const uint4* __restrict__ Wimg,
        const float* __restrict__ bias, uint4* __restrict__ outHi,
        uint4* __restrict__ outLo, int M, int ntiles)
{
    extern __shared__ char smem[];
    const uint32_t sb = smem_u32(smem);
    const uint32_t sW = sb + 131072;

    const int tid = threadIdx.x;
    const int wid = tid >> 5;
    const int L   = tid & 31;
    const int warpM = wid >> 2, warpN = wid & 3;
    const int fi = L & 15, fswz = (fi & 7) << 4, fk8 = (L >> 4) * 8;
    const int sr = tid >> 2, sq = tid & 3;   // convert mapping: 4 thr/row

    for (int i = tid; i < 4096; i += 512) cpa16(sW + i * 16, Wimg + i);
    // prologue: fp32 copy of first tile (swizzled, zero-padded)
    {
        int m0 = blockIdx.x * 128;
        for (int i = tid; i < 4096; i += 512) {
            int r = i >> 5, cc = i & 31;
            int gr = m0 + r;
            int sz = (gr < M) ? 16 : 0;
            const float* src = A + (size_t)(gr < M ? gr : 0) * 128 + cc * 4;
            cpa16z(sb + f32_off(r, cc), src, sz);
        }
    }
    CP_COMMIT();

    int cur = 0;
    for (int tile = blockIdx.x; tile < ntiles; tile += gridDim.x) {
        CP_WAIT0();
        __syncthreads();

        const uint32_t sA = sb + cur * 65536;

        // read fp32 (conflict-free swizzled) into regs
        float4 v[8];
#pragma unroll
        for (int j = 0; j < 8; ++j)
            v[j] = *(const float4*)(smem + cur * 65536 +
                                    f32_off(sr, sq * 8 + j));

        // prefetch next tile's fp32 into the other buffer
        int nxt = tile + gridDim.x;
        if (nxt < ntiles) {
            uint32_t dst = sb + (cur ^ 1) * 65536;
            int m0n = nxt * 128;
            for (int i = tid; i < 4096; i += 512) {
                int r = i >> 5, cc = i & 31;
                int gr = m0n + r;
                int sz = (gr < M) ? 16 : 0;
                const float* src = A + (size_t)(gr < M ? gr : 0) * 128 + cc * 4;
                cpa16z(dst + f32_off(r, cc), src, sz);
            }
        }
        CP_COMMIT();
        __syncthreads();   // all fp32 reads of cur done

        // in-place convert: write hi (0..32K) / lo (32..64K) images
#pragma unroll
        for (int j = 0; j < 8; ++j) {
            float4 a = v[j];
            float hx = __bfloat162float(__float2bfloat16(a.x));
            float hy = __bfloat162float(__float2bfloat16(a.y));
            float hz = __bfloat162float(__float2bfloat16(a.z));
            float hw = __bfloat162float(__float2bfloat16(a.w));
            uint32_t off = img_off(sr, (sq * 8 + j) * 4);
            *(uint2*)(smem + cur * 65536 + off) =
                make_uint2(packbf(a.x, a.y), packbf(a.z, a.w));
            *(uint2*)(smem + cur * 65536 + 32768 + off) =
                make_uint2(packbf(a.x - hx, a.y - hy), packbf(a.z - hz, a.w - hw));
        }
        __syncthreads();

        float acc[2][4][4];
        tile_mainloop(acc, sA, sA + 32768, sW, sW + 32768,
                      warpM, warpN, fi, fswz, fk8);

        // epilogue: relu+bias, split, write hi/lo images
        const int m0 = tile * 128;
        char* hB = (char*)outHi + (size_t)tile * 32768;
        char* lB = (char*)outLo + (size_t)tile * 32768;
#pragma unroll
        for (int mt = 0; mt < 2; ++mt) {
            int r0 = warpM * 32 + mt * 16 + (L >> 2);
            int r1 = r0 + 8;
#pragma unroll
            for (int ns = 0; ns < 4; ++ns) {
                int c = warpN * 32 + ns * 8 + (L & 3) * 2;
                float b0 = bias[c], b1 = bias[c + 1];
                float v00 = fmaxf(acc[mt][ns][0] + b0, 0.f);
                float v01 = fmaxf(acc[mt][ns][1] + b1, 0.f);
                float v10 = fmaxf(acc[mt][ns][2] + b0, 0.f);
                float v11 = fmaxf(acc[mt][ns][3] + b1, 0.f);
                if (m0 + r0 < M) {
                    uint32_t off = img_off(r0, c);
                    float h0 = __bfloat162float(__float2bfloat16(v00));
                    float h1 = __bfloat162float(__float2bfloat16(v01));
                    *(unsigned*)(hB + off) = packbf(v00, v01);
                    *(unsigned*)(lB + off) = packbf(v00 - h0, v01 - h1);
                }
                if (m0 + r1 < M) {
                    uint32_t off = img_off(r1, c);
                    float h0 = __bfloat162float(__float2bfloat16(v10));
                    float h1 = __bfloat162float(__float2bfloat16(v11));
                    *(unsigned*)(hB + off) = packbf(v10, v11);
                    *(unsigned*)(lB + off) = packbf(v10 - h0, v11 - h1);
                }
            }
        }
        cur ^= 1;
    }
}

// ---------------------------------------------------------------------------
// gemm_b: image input, cp.async double-buffered; fp32 output.
// smem: [A0 64K][A1 64K][W 64K] = 192 KB.
// ---------------------------------------------------------------------------
__global__ void __launch_bounds__(512, 1)
gemm_b(const uint4* __restrict__ hiImg, const uint4* __restrict__ loImg,
       const uint4* __restrict__ Wimg, const float* __restrict__ bias,
       const int* __restrict__ rowcnt, float* __restrict__ C,
       int M, int ntiles, int do_relu)
{
    extern __shared__ char smem[];
    const uint32_t sb = smem_u32(smem);
    const uint32_t sW = sb + 131072;

    const int tid = threadIdx.x;
    const int wid = tid >> 5;
    const int L   = tid & 31;
    const int warpM = wid >> 2, warpN = wid & 3;
    const int fi = L & 15, fswz = (fi & 7) << 4, fk8 = (L >> 4) * 8;

    for (int i = tid; i < 4096; i += 512) cpa16(sW + i * 16, Wimg + i);
    {
        int t0 = blockIdx.x;
        if (t0 < ntiles) {
            const uint4* sH = hiImg + (size_t)t0 * 2048;
            const uint4* sL = loImg + (size_t)t0 * 2048;
            for (int i = tid; i < 2048; i += 512) {
                cpa16(sb + i * 16, sH + i);
                cpa16(sb + 32768 + i * 16, sL + i);
            }
        }
    }
    CP_COMMIT();

    int cur = 0;
    for (int tile = blockIdx.x; tile < ntiles; tile += gridDim.x) {
        CP_WAIT0();
        __syncthreads();

        int nxt = tile + gridDim.x;
        if (nxt < ntiles) {
            uint32_t dst = sb + (cur ^ 1) * 65536;
            const uint4* sH = hiImg + (size_t)nxt * 2048;
            const uint4* sL = loImg + (size_t)nxt * 2048;
            for (int i = tid; i < 2048; i += 512) {
                cpa16(dst + i * 16, sH + i);
                cpa16(dst + 32768 + i * 16, sL + i);
            }
        }
        CP_COMMIT();

        const uint32_t sAh = sb + cur * 65536;
        float acc[2][4][4];
        tile_mainloop(acc, sAh, sAh + 32768, sW, sW + 32768,
                      warpM, warpN, fi, fswz, fk8);

        epi_f32(acc, C, bias, rowcnt, tile * 128, M, do_relu, warpM, warpN, L);
        cur ^= 1;
    }
}

// ---------------------------------------------------------------------------
// gemm_pq2: split grid. CTAs [0,74) compute P (W1a, +b1); [74,148) compute Q.
// Double-buffered like gemm_b.
// ---------------------------------------------------------------------------
__global__ void __launch_bounds__(512, 1)
gemm_pq2(const uint4* __restrict__ hiImg, const uint4* __restrict__ loImg,
         const uint4* __restrict__ Wa, const uint4* __restrict__ Wb,
         const float* __restrict__ b1, float* __restrict__ P,
         float* __restrict__ Q, int M, int ntiles)
{
    extern __shared__ char smem[];
    const uint32_t sb = smem_u32(smem);
    const uint32_t sW = sb + 131072;

    const int half = (blockIdx.x >= 74) ? 1 : 0;
    const int base = blockIdx.x - half * 74;
    const uint4* Wimg = half ? Wb : Wa;
    float* C = half ? Q : P;
    const float* bias = half ? nullptr : b1;

    const int tid = threadIdx.x;
    const int wid = tid >> 5;
    const int L   = tid & 31;
    const int warpM = wid >> 2, warpN = wid & 3;
    const int fi = L & 15, fswz = (fi & 7) << 4, fk8 = (L >> 4) * 8;

    for (int i = tid; i < 4096; i += 512) cpa16(sW + i * 16, Wimg + i);
    {
        const uint4* sH = hiImg + (size_t)base * 2048;
        const uint4* sL = loImg + (size_t)base * 2048;
        for (int i = tid; i < 2048; i += 512) {
            cpa16(sb + i * 16, sH + i);
            cpa16(sb + 32768 + i * 16, sL + i);
        }
    }
    CP_COMMIT();

    int cur = 0;
    for (int tile = base; tile < ntiles; tile += 74) {
        CP_WAIT0();
        __syncthreads();

        int nxt = tile + 74;
        if (nxt < ntiles) {
            uint32_t dst = sb + (cur ^ 1) * 65536;
            const uint4* sH = hiImg + (size_t)nxt * 2048;
            const uint4* sL = loImg + (size_t)nxt * 2048;
            for (int i = tid; i < 2048; i += 512) {
                cpa16(dst + i * 16, sH + i);
                cpa16(dst + 32768 + i * 16, sL + i);
            }
        }
        CP_COMMIT();

        const uint32_t sAh = sb + cur * 65536;
        float acc[2][4][4];
        tile_mainloop(acc, sAh, sAh + 32768, sW, sW + 32768,
                      warpM, warpN, fi, fswz, fk8);

        epi_f32(acc, C, bias, nullptr, tile * 128, M, 0, warpM, warpN, L);
        cur ^= 1;
    }
}

// ---------------------------------------------------------------------------
__global__ void __launch_bounds__(256)
zero_kernel()
{
    int idx = blockIdx.x * blockDim.x + threadIdx.x;
    int stride = gridDim.x * blockDim.x;
    for (int i = idx; i < NODES; i += stride) g_cnt[i] = 0;
    if (idx == 0) g_novf = 0;
}

__global__ void __launch_bounds__(256)
bucket_kernel(const int* __restrict__ ei)
{
    int e = blockIdx.x * blockDim.x + threadIdx.x;
    if (e >= EDGES) return;
    int s = ei[e];
    int d = ei[EDGES + e];
    int slot = atomicAdd(&g_cnt[d], 1);
    if (slot < CAP) {
        g_bucket[(size_t)d * CAP + slot] = s;
    } else {
        int o = atomicAdd(&g_novf, 1);
        if (o < OVFMAX) g_ovf[o] = make_int2(s, d);
    }
}

// Warp per node: S[d] = sum relu(P[d]+Q[src]); write S as bf16 hi/lo images.
__global__ void __launch_bounds__(256)
node_kernel()
{
    int d    = (blockIdx.x * blockDim.x + threadIdx.x) >> 5;
    int lane = threadIdx.x & 31;
    if (d >= NODES) return;

    int n = g_cnt[d];
    if (n > CAP) n = CAP;

    float4 p = ((const float4*)(g_P + (size_t)d * HID))[lane];
    float4 acc = make_float4(0.f, 0.f, 0.f, 0.f);
    const int* bkt = g_bucket + (size_t)d * CAP;
#pragma unroll 2
    for (int i = 0; i < n; ++i) {
        int s = __ldg(bkt + i);
        float4 q = ((const float4*)(g_Q + (size_t)s * HID))[lane];
        acc.x += fmaxf(p.x + q.x, 0.f);
        acc.y += fmaxf(p.y + q.y, 0.f);
        acc.z += fmaxf(p.z + q.z, 0.f);
        acc.w += fmaxf(p.w + q.w, 0.f);
    }
    int r = d & 127;
    uint32_t off = img_off(r, lane * 4);
    char* hB = (char*)g_sHi + (size_t)(d >> 7) * 32768;
    char* lB = (char*)g_sLo + (size_t)(d >> 7) * 32768;
    float hx = __bfloat162float(__float2bfloat16(acc.x));
    float hy = __bfloat162float(__float2bfloat16(acc.y));
    float hz = __bfloat162float(__float2bfloat16(acc.z));
    float hw = __bfloat162float(__float2bfloat16(acc.w));
    *(uint2*)(hB + off) = make_uint2(packbf(acc.x, acc.y), packbf(acc.z, acc.w));
    *(uint2*)(lB + off) = make_uint2(packbf(acc.x - hx, acc.y - hy),
                                     packbf(acc.z - hz, acc.w - hw));
}

// Serial overflow fixup (single warp; expected empty). RMW on S images.
__global__ void __launch_bounds__(32)
fixup_kernel()
{
    int total = g_novf;
    if (total > OVFMAX) total = OVFMAX;
    int lane = threadIdx.x;
    for (int j = 0; j < total; ++j) {
        int2 e = g_ovf[j];
        float4 p = ((const float4*)(g_P + (size_t)e.y * HID))[lane];
        float4 q = ((const float4*)(g_Q + (size_t)e.x * HID))[lane];
        int r = e.y & 127;
        uint32_t off = img_off(r, lane * 4);
        char* hB = (char*)g_sHi + (size_t)(e.y >> 7) * 32768;
        char* lB = (char*)g_sLo + (size_t)(e.y >> 7) * 32768;
        uint2 hh = *(uint2*)(hB + off);
        uint2 ll = *(uint2*)(lB + off);
        __nv_bfloat162 h0 = *(__nv_bfloat162*)&hh.x, h1 = *(__nv_bfloat162*)&hh.y;
        __nv_bfloat162 l0 = *(__nv_bfloat162*)&ll.x, l1 = *(__nv_bfloat162*)&ll.y;
        float vx = __bfloat162float(h0.x) + __bfloat162float(l0.x) + fmaxf(p.x + q.x, 0.f);
        float vy = __bfloat162float(h0.y) + __bfloat162float(l0.y) + fmaxf(p.y + q.y, 0.f);
        float vz = __bfloat162float(h1.x) + __bfloat162float(l1.x) + fmaxf(p.z + q.z, 0.f);
        float vw = __bfloat162float(h1.y) + __bfloat162float(l1.y) + fmaxf(p.w + q.w, 0.f);
        float hx = __bfloat162float(__float2bfloat16(vx));
        float hy = __bfloat162float(__float2bfloat16(vy));
        float hz = __bfloat162float(__float2bfloat16(vz));
        float hw = __bfloat162float(__float2bfloat16(vw));
        *(uint2*)(hB + off) = make_uint2(packbf(vx, vy), packbf(vz, vw));
        *(uint2*)(lB + off) = make_uint2(packbf(vx - hx, vy - hy),
                                         packbf(vz - hz, vw - hw));
        __syncwarp();
    }
}

__global__ void __launch_bounds__(256)
out_kernel(const float* __restrict__ H2, const float* __restrict__ Wc,
           const float* __restrict__ bc, float* __restrict__ out)
{
    int gw   = (blockIdx.x * blockDim.x + threadIdx.x) >> 5;
    int lane = threadIdx.x & 31;
    if (gw >= NODES) return;

    float4 hv  = ((const float4*)(H2 + (size_t)gw * HID))[lane];
    float4 w01 = ((const float4*)Wc)[lane * 2];
    float4 w23 = ((const float4*)Wc)[lane * 2 + 1];

    float a0 = hv.x * w01.x + hv.y * w01.z + hv.z * w23.x + hv.w * w23.z;
    float a1 = hv.x * w01.y + hv.y * w01.w + hv.z * w23.y + hv.w * w23.w;
#pragma unroll
    for (int off = 16; off > 0; off >>= 1) {
        a0 += __shfl_xor_sync(0xffffffffu, a0, off);
        a1 += __shfl_xor_sync(0xffffffffu, a1, off);
    }
    if (lane == 0) {
        out[(size_t)gw * 2]     = a0 + bc[0];
        out[(size_t)gw * 2 + 1] = a1 + bc[1];
    }
}

// ---------------------------------------------------------------------------
extern "C" void kernel_launch(void* const* d_in, const int* in_sizes, int n_in,
                              void* d_out, int out_size)
{
    const float* x    = (const float*)d_in[0];
    const int*   ei   = (const int*)d_in[1];
    const float* W_in = (const float*)d_in[2];
    const float* b_in = (const float*)d_in[3];
    const float* W1   = (const float*)d_in[4];
    const float* b1   = (const float*)d_in[5];
    const float* W2   = (const float*)d_in[6];
    const float* b2   = (const float*)d_in[7];
    const float* Wc   = (const float*)d_in[8];
    const float* bc   = (const float*)d_in[9];
    float*       out  = (float*)d_out;

    void *ph2, *pP, *pQ, *pcnt, *pWin, *pW1a, *pW1b, *pW2;
    void *phHi, *phLo, *psHi, *psLo;
    cudaGetSymbolAddress(&ph2,  g_h2);
    cudaGetSymbolAddress(&pP,   g_P);
    cudaGetSymbolAddress(&pQ,   g_Q);
    cudaGetSymbolAddress(&pcnt, g_cnt);
    cudaGetSymbolAddress(&pWin, g_iWin);
    cudaGetSymbolAddress(&pW1a, g_iW1a);
    cudaGetSymbolAddress(&pW1b, g_iW1b);
    cudaGetSymbolAddress(&pW2,  g_iW2);
    cudaGetSymbolAddress(&phHi, g_hHi);
    cudaGetSymbolAddress(&phLo, g_hLo);
    cudaGetSymbolAddress(&psHi, g_sHi);
    cudaGetSymbolAddress(&psLo, g_sLo);

    cudaFuncSetAttribute(gemm_xa, cudaFuncAttributeMaxDynamicSharedMemorySize,
                         192 * 1024);
    cudaFuncSetAttribute(gemm_b, cudaFuncAttributeMaxDynamicSharedMemorySize,
                         192 * 1024);
    cudaFuncSetAttribute(gemm_pq2, cudaFuncAttributeMaxDynamicSharedMemorySize,
                         192 * 1024);

    const int M = NODES;
    const int GRID = 148;

    prep_kernel<<<256, 256>>>(W_in, W1, W2);
    zero_kernel<<<256, 256>>>();
    bucket_kernel<<<(EDGES + 255) / 256, 256>>>(ei);

    // 1) h images = split(relu(x @ Win + b_in)), pipelined fp32->image convert
    gemm_xa<<<GRID, 512, 192 * 1024>>>(x, (const uint4*)pWin, b_in,
                                       (uint4*)phHi, (uint4*)phLo, M, NTILES);
    // 2+3) P = h @ W1a + b1 ; Q = h @ W1b (split-grid fused)
    gemm_pq2<<<GRID, 512, 192 * 1024>>>((const uint4*)phHi, (const uint4*)phLo,
                                        (const uint4*)pW1a, (const uint4*)pW1b,
                                        b1, (float*)pP, (float*)pQ, M, NTILES);
    // 4) S images = split( sum_e relu(P[d]+Q[s]) )
    node_kernel<<<(NODES * 32 + 255) / 256, 256>>>();
    fixup_kernel<<<1, 32>>>();
    // 5) h2 = relu(S @ W2 + deg*b2)
    gemm_b<<<GRID, 512, 192 * 1024>>>((const uint4*)psHi, (const uint4*)psLo,
                                      (const uint4*)pW2, b2, (const int*)pcnt,
                                      (float*)ph2, M, NTILES, 1);
    // 6) out = h2 @ Wc + bc
    out_kernel<<<(NODES * 32 + 255) / 256, 256>>>((const float*)ph2, Wc, bc, out);
}